// round 4
// baseline (speedup 1.0000x reference)
#include <cuda_runtime.h>

#define B_ 32
#define T_ 2048
#define F_ 128
#define U_ 128
#define G_ 384   /* 3U */
#define C_ 11
#define R_ (B_*T_)  /* 65536 rows */

// ---------------------------------------------------------------------------
// Scratch (device globals: no runtime allocation allowed)
// ---------------------------------------------------------------------------
__device__ float g_xg[2][R_ * G_];      // input projections per direction
__device__ float g_hs[R_ * 2 * U_];     // concat hidden states [b*T+t][256]

// ---------------------------------------------------------------------------
// Packed fp32x2 helpers
// ---------------------------------------------------------------------------
__device__ __forceinline__ unsigned long long ffma2(unsigned long long a,
                                                    unsigned long long b,
                                                    unsigned long long c) {
    unsigned long long d;
    asm("fma.rn.f32x2 %0, %1, %2, %3;" : "=l"(d) : "l"(a), "l"(b), "l"(c));
    return d;
}
__device__ __forceinline__ unsigned long long pack2(float x, float y) {
    unsigned long long r;
    asm("mov.b64 %0, {%1, %2};" : "=l"(r) : "f"(x), "f"(y));
    return r;
}
__device__ __forceinline__ float sum2(unsigned long long v) {
    float lo, hi;
    asm("mov.b64 {%0, %1}, %2;" : "=f"(lo), "=f"(hi) : "l"(v));
    return lo + hi;
}
__device__ __forceinline__ float sigf(float x) {
    return __fdividef(1.f, 1.f + __expf(-x));
}

// ---------------------------------------------------------------------------
// Phase 1: xg[dir] = x @ W[dir] + b[dir][0] (+ b[dir][1] folded for z,r cols)
// C[65536,384] = A[65536,128] * W[128,384]. Round-1 tiling (measured 366us):
// TM=64, TN=64, TK=32; 256 threads; 4x4 micro-tile per thread.
// ---------------------------------------------------------------------------
__global__ __launch_bounds__(256) void proj_kernel(
    const float* __restrict__ x,
    const float* __restrict__ Wf, const float* __restrict__ bf,
    const float* __restrict__ Wb, const float* __restrict__ bb)
{
    const int dir = blockIdx.z;
    const float* __restrict__ W    = dir ? Wb : Wf;
    const float* __restrict__ bias = dir ? bb : bf;   // [2,384]
    float* __restrict__ Cout = g_xg[dir];

    const int r0 = blockIdx.x * 64;
    const int c0 = blockIdx.y * 64;

    __shared__ float As[64 * 36];   // [i][k], row stride 36
    __shared__ float Bs[32 * 64];   // [k][j]

    const int tid = threadIdx.x;
    const int tx  = tid & 15;
    const int ty  = tid >> 4;

    float acc[4][4];
    #pragma unroll
    for (int i = 0; i < 4; i++)
        #pragma unroll
        for (int j = 0; j < 4; j++) acc[i][j] = 0.f;

    for (int k0 = 0; k0 < F_; k0 += 32) {
        #pragma unroll
        for (int q = 0; q < 2; q++) {
            int idx = tid + 256 * q;
            int i   = idx >> 3;
            int kk4 = (idx & 7) << 2;
            float4 v = *(const float4*)(x + (size_t)(r0 + i) * F_ + k0 + kk4);
            *(float4*)(As + i * 36 + kk4) = v;
        }
        #pragma unroll
        for (int q = 0; q < 2; q++) {
            int idx = tid + 256 * q;
            int kk  = idx >> 4;
            int j4  = (idx & 15) << 2;
            float4 v = *(const float4*)(W + (size_t)(k0 + kk) * G_ + c0 + j4);
            *(float4*)(Bs + kk * 64 + j4) = v;
        }
        __syncthreads();

        #pragma unroll
        for (int kk = 0; kk < 32; kk++) {
            float a0 = As[(ty * 4 + 0) * 36 + kk];
            float a1 = As[(ty * 4 + 1) * 36 + kk];
            float a2 = As[(ty * 4 + 2) * 36 + kk];
            float a3 = As[(ty * 4 + 3) * 36 + kk];
            float4 b = *(const float4*)(Bs + kk * 64 + tx * 4);
            acc[0][0] += a0 * b.x; acc[0][1] += a0 * b.y; acc[0][2] += a0 * b.z; acc[0][3] += a0 * b.w;
            acc[1][0] += a1 * b.x; acc[1][1] += a1 * b.y; acc[1][2] += a1 * b.z; acc[1][3] += a1 * b.w;
            acc[2][0] += a2 * b.x; acc[2][1] += a2 * b.y; acc[2][2] += a2 * b.z; acc[2][3] += a2 * b.w;
            acc[3][0] += a3 * b.x; acc[3][1] += a3 * b.y; acc[3][2] += a3 * b.z; acc[3][3] += a3 * b.w;
        }
        __syncthreads();
    }

    #pragma unroll
    for (int di = 0; di < 4; di++) {
        int r = r0 + ty * 4 + di;
        int c = c0 + tx * 4;
        float4 v;
        // Fold input bias b[0]; ALSO fold recurrent bias b[1] for z and r
        // gate columns (c < 256), since those enter the gates as a plain sum.
        // The h-gate recurrent bias (c >= 256) is multiplied by r in the GRU,
        // so it stays in the gru kernel.
        #pragma unroll
        for (int jj = 0; jj < 4; jj++) {
            float bsum = bias[c + jj] + ((c + jj) < 2 * U_ ? bias[G_ + c + jj] : 0.f);
            ((float*)&v)[jj] = acc[di][jj] + bsum;
        }
        *(float4*)(Cout + (size_t)r * G_ + c) = v;
    }
}

// ---------------------------------------------------------------------------
// Phase 2: GRU recurrence. One persistent block per (batch, direction).
// 512 threads: thread (u, q) with u = tid>>2 (hidden unit), q = tid&3
// (K-quarter). Each thread holds the z/r/h gate columns for its 32-wide K
// slice in registers (48 packed u64 = 96 regs). Per step:
//   - 8 LDS.128 of the h quarter, 48 ffma2 (3 independent chains)
//   - butterfly shfl over the 4-lane group -> full dot products in all lanes
//   - activation computed redundantly by all 4 lanes (bitwise identical)
//   - lane q==0 writes h to the other smem buffer, q==3 writes gmem output
//   - ONE __syncthreads per step (double-buffered h)
// ---------------------------------------------------------------------------
__global__ __launch_bounds__(512, 1) void gru_kernel(
    const float* __restrict__ Uf, const float* __restrict__ bf,
    const float* __restrict__ Ub, const float* __restrict__ bb)
{
    const int b   = blockIdx.x;
    const int dir = blockIdx.y;
    const int tid = threadIdx.x;
    const int u   = tid >> 2;
    const int q   = tid & 3;

    const float* __restrict__ Um   = dir ? Ub : Uf;
    const float* __restrict__ bias = dir ? bb : bf;
    const float* __restrict__ xg   = g_xg[dir] + (size_t)b * T_ * G_;
    float* __restrict__ hout = g_hs + (size_t)b * T_ * (2 * U_) + (dir ? U_ : 0);

    const int cz = u, cr = u + U_, ch = u + 2 * U_;
    const float bh = bias[G_ + ch];   // only h-gate recurrent bias needed here

    // Gate columns for this K-quarter, packed by k-pairs.
    unsigned long long uz[16], ur[16], uh[16];
    const int k0 = q * 32;
    #pragma unroll
    for (int j = 0; j < 16; j++) {
        const int k = k0 + 2 * j;
        uz[j] = pack2(Um[(size_t)k * G_ + cz], Um[(size_t)(k + 1) * G_ + cz]);
        ur[j] = pack2(Um[(size_t)k * G_ + cr], Um[(size_t)(k + 1) * G_ + cr]);
        uh[j] = pack2(Um[(size_t)k * G_ + ch], Um[(size_t)(k + 1) * G_ + ch]);
    }

    __shared__ __align__(16) float hbuf[2][U_];
    if (tid < U_) { hbuf[0][tid] = 0.f; hbuf[1][tid] = 0.f; }
    __syncthreads();

    const int stepd = dir ? -1 : 1;
    int t = dir ? (T_ - 1) : 0;
    float hprev = 0.f;

    // z,r recurrent biases are pre-folded into xg by proj_kernel.
    float xz = xg[(size_t)t * G_ + cz];
    float xr = xg[(size_t)t * G_ + cr];
    float xh = xg[(size_t)t * G_ + ch];

    int p = 0;
    for (int s = 0; s < T_; s++) {
        const int tn = t + stepd;
        const int tc = (tn < 0) ? 0 : (tn >= T_ ? T_ - 1 : tn);
        // Prefetch next timestep's projections (hidden under the dot).
        const float nxz = xg[(size_t)tc * G_ + cz];
        const float nxr = xg[(size_t)tc * G_ + cr];
        const float nxh = xg[(size_t)tc * G_ + ch];

        // Partial dots over this thread's K-quarter (3 independent chains).
        const ulonglong2* hp = (const ulonglong2*)(hbuf[p] + k0);
        unsigned long long az = 0ull, ag = 0ull, ah = 0ull;
        #pragma unroll
        for (int j = 0; j < 8; j++) {
            const ulonglong2 hv = hp[j];
            az = ffma2(hv.x, uz[2 * j],     az);
            ag = ffma2(hv.x, ur[2 * j],     ag);
            ah = ffma2(hv.x, uh[2 * j],     ah);
            az = ffma2(hv.y, uz[2 * j + 1], az);
            ag = ffma2(hv.y, ur[2 * j + 1], ag);
            ah = ffma2(hv.y, uh[2 * j + 1], ah);
        }
        float pz = sum2(az);
        float pr = sum2(ag);
        float ph = sum2(ah);

        // Butterfly over the 4-lane (u-aligned) group: all lanes get full sums.
        pz += __shfl_xor_sync(0xffffffffu, pz, 1);
        pr += __shfl_xor_sync(0xffffffffu, pr, 1);
        ph += __shfl_xor_sync(0xffffffffu, ph, 1);
        pz += __shfl_xor_sync(0xffffffffu, pz, 2);
        pr += __shfl_xor_sync(0xffffffffu, pr, 2);
        ph += __shfl_xor_sync(0xffffffffu, ph, 2);

        const float z  = sigf(xz + pz);
        const float r  = sigf(xr + pr);
        const float hh = fmaxf(xh + r * (ph + bh), 0.f);
        const float hn = fmaf(z, hprev - hh, hh);   // z*h + (1-z)*hh
        hprev = hn;

        if (q == 0)      hbuf[p ^ 1][u] = hn;
        else if (q == 3) hout[(size_t)t * (2 * U_) + u] = hn;
        __syncthreads();

        p ^= 1;
        t = tn;
        xz = nxz; xr = nxr; xh = nxh;
    }
}

// ---------------------------------------------------------------------------
// Phase 3: logits = h_cat @ Wd + bd ; softmax over C. One warp per (b,t) row.
// ---------------------------------------------------------------------------
__global__ __launch_bounds__(128) void dense_kernel(
    const float* __restrict__ Wd, const float* __restrict__ bd,
    float* __restrict__ out)
{
    __shared__ float wds[2 * U_ * C_];
    __shared__ float bds[C_];
    const int tid = threadIdx.x;
    for (int i = tid; i < 2 * U_ * C_; i += 128) wds[i] = Wd[i];
    if (tid < C_) bds[tid] = bd[tid];
    __syncthreads();

    const int w = tid >> 5;
    const int l = tid & 31;
    const size_t row = (size_t)blockIdx.x * 4 + w;

    const float* __restrict__ h = g_hs + row * (2 * U_);
    float hv[8];
    #pragma unroll
    for (int qq = 0; qq < 8; qq++) hv[qq] = h[l + 32 * qq];

    float logit[C_];
    #pragma unroll
    for (int c = 0; c < C_; c++) {
        float a = 0.f;
        #pragma unroll
        for (int qq = 0; qq < 8; qq++) a += hv[qq] * wds[(l + 32 * qq) * C_ + c];
        logit[c] = a;
    }
    #pragma unroll
    for (int c = 0; c < C_; c++) {
        #pragma unroll
        for (int off = 16; off; off >>= 1)
            logit[c] += __shfl_xor_sync(0xffffffffu, logit[c], off);
        logit[c] += bds[c];
    }

    float m = logit[0];
    #pragma unroll
    for (int c = 1; c < C_; c++) m = fmaxf(m, logit[c]);
    float e[C_], ssum = 0.f;
    #pragma unroll
    for (int c = 0; c < C_; c++) { e[c] = __expf(logit[c] - m); ssum += e[c]; }
    const float inv = __fdividef(1.f, ssum);
    if (l == 0) {
        #pragma unroll
        for (int c = 0; c < C_; c++) out[row * C_ + c] = e[c] * inv;
    }
}

// ---------------------------------------------------------------------------
extern "C" void kernel_launch(void* const* d_in, const int* in_sizes, int n_in,
                              void* d_out, int out_size)
{
    const float* x  = (const float*)d_in[0];
    const float* Wf = (const float*)d_in[1];
    const float* Uf = (const float*)d_in[2];
    const float* bf = (const float*)d_in[3];
    const float* Wb = (const float*)d_in[4];
    const float* Ub = (const float*)d_in[5];
    const float* bb = (const float*)d_in[6];
    const float* Wd = (const float*)d_in[7];
    const float* bd = (const float*)d_in[8];
    float* out = (float*)d_out;

    proj_kernel<<<dim3(R_ / 64, G_ / 64, 2), 256>>>(x, Wf, bf, Wb, bb);
    gru_kernel<<<dim3(B_, 2), 512>>>(Uf, bf, Ub, bb);
    dense_kernel<<<R_ / 4, 128>>>(Wd, bd, out);
}